// round 1
// baseline (speedup 1.0000x reference)
#include <cuda_runtime.h>
#include <math.h>

#define B_   16
#define C_   1024
#define BC_  (B_ * C_)
#define EPSf  1e-12f
#define TINYf 1e-9f

// Output layout (flattened tuple, fp32):
//  [0, BC)                     soft_lower        (B,C)
//  [BC, 2BC)                   soft_upper        (B,C)
//  [2BC, 2BC+BCC)              final_lower_coef  (B,C,C)
//  [2BC+BCC, 2BC+2BCC)         final_upper_coef  (B,C,C)
//  [2BC+2BCC, 2BC+2BCC+BC)     final_lower_bias  (B,C)
//  [2BC+2BCC+BC, ...)          final_upper_bias  (B,C)
#define BCC_    ((size_t)BC_ * (size_t)C_)          // 16,777,216
#define OFF_SL  ((size_t)0)
#define OFF_SU  ((size_t)BC_)
#define OFF_LC  ((size_t)(2 * BC_))
#define OFF_UC  ((size_t)(2 * BC_) + BCC_)
#define OFF_LB  ((size_t)(2 * BC_) + 2 * BCC_)
#define OFF_UB  ((size_t)(2 * BC_) + 2 * BCC_ + BC_)

// Precomputed per-element exps (scratch: __device__ globals, no allocation)
__device__ float g_El[BC_];   // exp(l)
__device__ float g_Eu[BC_];   // exp(u)
__device__ float g_Em[BC_];   // exp(0.5*(l+u))

__global__ void pre_kernel(const float* __restrict__ lower,
                           const float* __restrict__ upper) {
    int idx = blockIdx.x * blockDim.x + threadIdx.x;
    if (idx < BC_) {
        float l = lower[idx];
        float u = upper[idx];
        g_El[idx] = expf(l);
        g_Eu[idx] = expf(u);
        g_Em[idx] = expf(0.5f * (l + u));
    }
}

// One block per output row (b, i). 256 threads * 4 j's each = C columns.
__global__ __launch_bounds__(256) void bs_kernel(
    const float* __restrict__ lower,
    const float* __restrict__ upper,
    float* __restrict__ out)
{
    const int row = blockIdx.x;              // b*C + i
    const int b   = row >> 10;
    const int i   = row & (C_ - 1);
    const int tid = threadIdx.x;
    const int j0  = tid << 2;

    const float* __restrict__ lrow = lower + (size_t)b * C_;
    const float* __restrict__ urow = upper + (size_t)b * C_;

    // per-row (i) scalars: 3 exps per block, negligible
    const float l_i = lrow[i];
    const float u_i = urow[i];
    const float EuN = expf(-u_i);                 // exp(-u_i)
    const float ElN = expf(-l_i);                 // exp(-l_i)
    const float EmN = expf(-0.5f * (l_i + u_i));  // exp(-0.5*(l_i+u_i))

    // vectorized per-j loads (L1/L2 resident: only 20KB unique per batch row set)
    float4 lj  = *reinterpret_cast<const float4*>(lrow + j0);
    float4 uj  = *reinterpret_cast<const float4*>(urow + j0);
    float4 Elj = *reinterpret_cast<const float4*>(g_El + (size_t)b * C_ + j0);
    float4 Euj = *reinterpret_cast<const float4*>(g_Eu + (size_t)b * C_ + j0);
    float4 Emj = *reinterpret_cast<const float4*>(g_Em + (size_t)b * C_ + j0);

    float au[4], al[4];
    float sSl = 0.f, sSu = 0.f, sAu = 0.f, sAl = 0.f, sBu = 0.f, sBl = 0.f;

    const float* ljp  = reinterpret_cast<const float*>(&lj);
    const float* ujp  = reinterpret_cast<const float*>(&uj);
    const float* Elp  = reinterpret_cast<const float*>(&Elj);
    const float* Eup  = reinterpret_cast<const float*>(&Euj);
    const float* Emp  = reinterpret_cast<const float*>(&Emj);

#pragma unroll
    for (int k = 0; k < 4; ++k) {
        float ld = ljp[k] - u_i;            // l_d = l_j - u_i
        float ud = ujp[k] - l_i;            // u_d = u_j - l_i
        float el = Elp[k] * EuN;            // exp(l_d)
        float eu = Eup[k] * ElN;            // exp(u_d)
        float dn = ud - ld;                 // denom >= 0
        float a_u = (eu - el) / (dn + EPSf);
        if (fabsf(dn) < TINYf) a_u = eu;
        float b_u = el - a_u * ld;
        float t   = 0.5f * (ld + ud);
        float a_l = Emp[k] * EmN;           // exp(t)
        float b_l = a_l * (1.0f - t);       // a_l - a_l*t
        if (j0 + k == i) {                  // zero diagonal contributions
            el = 0.f; eu = 0.f; a_u = 0.f; b_u = 0.f; a_l = 0.f; b_l = 0.f;
        }
        sSl += el;  sSu += eu;
        sAu += a_u; sAl += a_l;
        sBu += b_u; sBl += b_l;
        au[k] = a_u;
        al[k] = a_l;
    }

    // block reduction of 6 sums: shuffle within warp, smem across 8 warps
    float v0 = sSl, v1 = sSu, v2 = sAu, v3 = sAl, v4 = sBu, v5 = sBl;
#pragma unroll
    for (int m = 16; m > 0; m >>= 1) {
        v0 += __shfl_xor_sync(0xffffffffu, v0, m);
        v1 += __shfl_xor_sync(0xffffffffu, v1, m);
        v2 += __shfl_xor_sync(0xffffffffu, v2, m);
        v3 += __shfl_xor_sync(0xffffffffu, v3, m);
        v4 += __shfl_xor_sync(0xffffffffu, v4, m);
        v5 += __shfl_xor_sync(0xffffffffu, v5, m);
    }
    __shared__ float sred[6][8];
    const int warp = tid >> 5;
    const int lane = tid & 31;
    if (lane == 0) {
        sred[0][warp] = v0; sred[1][warp] = v1; sred[2][warp] = v2;
        sred[3][warp] = v3; sred[4][warp] = v4; sred[5][warp] = v5;
    }
    __syncthreads();
    float Sl = 0.f, Su = 0.f, Au = 0.f, Al = 0.f, Bu = 0.f, Bl = 0.f;
#pragma unroll
    for (int w = 0; w < 8; ++w) {
        Sl += sred[0][w]; Su += sred[1][w]; Au += sred[2][w];
        Al += sred[3][w]; Bu += sred[4][w]; Bl += sred[5][w];
    }

    // row scalars (computed redundantly in every thread; cheap)
    float g_l = 1.0f / (1.0f + Sl);
    float g_u = 1.0f / (1.0f + Su);
    float dg  = Su - Sl;
    float m_l = -g_u * g_u;                       // -1/(1+Su)^2
    float m_u = (g_u - g_l) / (dg + EPSf);
    if (fabsf(dg) < TINYf) m_u = m_l;
    float c_u = g_l - m_u * Sl;
    float c_l = g_u - m_l * Su;

    if (tid == 0) {
        out[OFF_SL + row] = fminf(fmaxf(g_u, 0.0f), 1.0f);  // soft_lower
        out[OFF_SU + row] = fminf(fmaxf(g_l, 0.0f), 1.0f);  // soft_upper
        out[OFF_LB + row] = m_l * Bl + c_l;                 // final_lower_bias
        out[OFF_UB + row] = m_u * Bu + c_u;                 // final_upper_bias
    }

    // phase 2: scale stashed a's and store coefs (float4, coalesced)
    const float diag_u = m_u * (-Au);
    const float diag_l = m_l * (-Al);
    float4 ocu, ocl;
    float* ocup = reinterpret_cast<float*>(&ocu);
    float* oclp = reinterpret_cast<float*>(&ocl);
#pragma unroll
    for (int k = 0; k < 4; ++k) {
        bool d = (j0 + k == i);
        ocup[k] = d ? diag_u : m_u * au[k];
        oclp[k] = d ? diag_l : m_l * al[k];
    }
    const size_t base = (size_t)row * C_ + j0;
    *reinterpret_cast<float4*>(out + OFF_LC + base) = ocl;
    *reinterpret_cast<float4*>(out + OFF_UC + base) = ocu;
}

extern "C" void kernel_launch(void* const* d_in, const int* in_sizes, int n_in,
                              void* d_out, int out_size) {
    const float* lower = (const float*)d_in[0];
    const float* upper = (const float*)d_in[1];
    float* out = (float*)d_out;
    pre_kernel<<<(BC_ + 255) / 256, 256>>>(lower, upper);
    bs_kernel<<<BC_, 256>>>(lower, upper, out);
}

// round 2
// speedup vs baseline: 1.1987x; 1.1987x over previous
#include <cuda_runtime.h>
#include <math.h>

#define B_   16
#define C_   1024
#define BC_  (B_ * C_)
#define EPSf  1e-12f
#define TINYf 1e-9f

#define BCC_    ((size_t)BC_ * (size_t)C_)
#define OFF_SL  ((size_t)0)
#define OFF_SU  ((size_t)BC_)
#define OFF_LC  ((size_t)(2 * BC_))
#define OFF_UC  ((size_t)(2 * BC_) + BCC_)
#define OFF_LB  ((size_t)(2 * BC_) + 2 * BCC_)
#define OFF_UB  ((size_t)(2 * BC_) + 2 * BCC_ + BC_)

// Precomputed per-element exponentials (no allocation: __device__ globals)
__device__ float g_El [BC_];   // exp(l)
__device__ float g_Eu [BC_];   // exp(u)
__device__ float g_ElN[BC_];   // exp(-l)
__device__ float g_EuN[BC_];   // exp(-u)

__global__ void pre_kernel(const float* __restrict__ lower,
                           const float* __restrict__ upper) {
    int idx = blockIdx.x * blockDim.x + threadIdx.x;
    if (idx < BC_) {
        float l = lower[idx];
        float u = upper[idx];
        g_El [idx] = expf(l);
        g_Eu [idx] = expf(u);
        g_ElN[idx] = expf(-l);
        g_EuN[idx] = expf(-u);
    }
}

__device__ __forceinline__ float sqrt_apx(float x) {
    float r;
    asm("sqrt.approx.f32 %0, %1;" : "=f"(r) : "f"(x));
    return r;
}

// One block per output row (b,i): 128 threads x 8 j's each.
__global__ __launch_bounds__(128) void bs_kernel(
    const float* __restrict__ lower,
    const float* __restrict__ upper,
    float* __restrict__ out)
{
    const int row = blockIdx.x;              // b*C + i
    const int b   = row >> 10;
    const int i   = row & (C_ - 1);
    const int tid = threadIdx.x;

    const float* __restrict__ lrow = lower + (size_t)b * C_;
    const float* __restrict__ urow = upper + (size_t)b * C_;
    const float* __restrict__ Elb  = g_El  + (size_t)b * C_;
    const float* __restrict__ Eub  = g_Eu  + (size_t)b * C_;

    // row-i scalars (uniform broadcasts; exps come from precomputed arrays)
    const float l_i = __ldg(lrow + i);
    const float u_i = __ldg(urow + i);
    const float ElN = g_ElN[row];            // exp(-l_i)
    const float EuN = g_EuN[row];            // exp(-u_i)

    float au[8], al[8];
    float sSl = 0.f, sSu = 0.f, sAu = 0.f, sAl = 0.f, sBu = 0.f, sBl = 0.f;

#pragma unroll
    for (int c = 0; c < 2; ++c) {
        const int jb = (tid << 3) + (c << 2);
        float4 lj  = *reinterpret_cast<const float4*>(lrow + jb);
        float4 uj  = *reinterpret_cast<const float4*>(urow + jb);
        float4 Elj = *reinterpret_cast<const float4*>(Elb  + jb);
        float4 Euj = *reinterpret_cast<const float4*>(Eub  + jb);
        const float* ljp = reinterpret_cast<const float*>(&lj);
        const float* ujp = reinterpret_cast<const float*>(&uj);
        const float* elp = reinterpret_cast<const float*>(&Elj);
        const float* eup = reinterpret_cast<const float*>(&Euj);
#pragma unroll
        for (int k = 0; k < 4; ++k) {
            float ld  = ljp[k] - u_i;        // l_d
            float ud  = ujp[k] - l_i;        // u_d
            float el  = elp[k] * EuN;        // exp(l_d)
            float eu  = eup[k] * ElN;        // exp(u_d)
            float dn  = ud - ld;             // >= 0
            float a_u = __fdividef(eu - el, dn + EPSf);
            if (dn < TINYf) a_u = eu;
            float b_u = el - a_u * ld;
            float a_l = sqrt_apx(el * eu);   // exp(0.5*(ld+ud))
            float h   = ld + ud;
            float b_l = a_l * fmaf(-0.5f, h, 1.0f);   // a_l*(1-t)
            sSl += el;  sSu += eu;
            sAu += a_u; sAl += a_l;
            sBu += b_u; sBl += b_l;
            au[(c << 2) + k] = a_u;
            al[(c << 2) + k] = a_l;
        }
    }

    // Diagonal element contributes ZERO in the reference: the owner thread
    // recomputes its j==i contribution (same arithmetic) and subtracts it.
    if (tid == (i >> 3)) {
        float ld  = l_i - u_i;
        float ud  = u_i - l_i;
        float el  = g_El[row] * EuN;
        float eu  = g_Eu[row] * ElN;
        float dn  = ud - ld;
        float a_u = __fdividef(eu - el, dn + EPSf);
        if (dn < TINYf) a_u = eu;
        float b_u = el - a_u * ld;
        float a_l = sqrt_apx(el * eu);
        float h   = ld + ud;
        float b_l = a_l * fmaf(-0.5f, h, 1.0f);
        sSl -= el;  sSu -= eu;
        sAu -= a_u; sAl -= a_l;
        sBu -= b_u; sBl -= b_l;
    }

    // warp-level reduction (4 warps)
    float v0 = sSl, v1 = sSu, v2 = sAu, v3 = sAl, v4 = sBu, v5 = sBl;
#pragma unroll
    for (int m = 16; m > 0; m >>= 1) {
        v0 += __shfl_xor_sync(0xffffffffu, v0, m);
        v1 += __shfl_xor_sync(0xffffffffu, v1, m);
        v2 += __shfl_xor_sync(0xffffffffu, v2, m);
        v3 += __shfl_xor_sync(0xffffffffu, v3, m);
        v4 += __shfl_xor_sync(0xffffffffu, v4, m);
        v5 += __shfl_xor_sync(0xffffffffu, v5, m);
    }
    __shared__ float part[4][8];
    __shared__ float bcast[4];
    const int warp = tid >> 5;
    if ((tid & 31) == 0) {
        part[warp][0] = v0; part[warp][1] = v1; part[warp][2] = v2;
        part[warp][3] = v3; part[warp][4] = v4; part[warp][5] = v5;
    }
    __syncthreads();
    if (tid == 0) {
        float Sl = part[0][0] + part[1][0] + part[2][0] + part[3][0];
        float Su = part[0][1] + part[1][1] + part[2][1] + part[3][1];
        float Au = part[0][2] + part[1][2] + part[2][2] + part[3][2];
        float Al = part[0][3] + part[1][3] + part[2][3] + part[3][3];
        float Bu = part[0][4] + part[1][4] + part[2][4] + part[3][4];
        float Bl = part[0][5] + part[1][5] + part[2][5] + part[3][5];

        float g_l = __fdividef(1.0f, 1.0f + Sl);
        float g_u = __fdividef(1.0f, 1.0f + Su);
        float dg  = Su - Sl;
        float m_l = -g_u * g_u;
        float m_u = __fdividef(g_u - g_l, dg + EPSf);
        if (fabsf(dg) < TINYf) m_u = m_l;
        float c_u = g_l - m_u * Sl;
        float c_l = g_u - m_l * Su;

        out[OFF_SL + row] = fminf(fmaxf(g_u, 0.0f), 1.0f);
        out[OFF_SU + row] = fminf(fmaxf(g_l, 0.0f), 1.0f);
        out[OFF_LB + row] = m_l * Bl + c_l;
        out[OFF_UB + row] = m_u * Bu + c_u;

        bcast[0] = m_u;
        bcast[1] = m_l;
        bcast[2] = m_u * (-Au);   // diag of upper coef
        bcast[3] = m_l * (-Al);   // diag of lower coef
    }
    __syncthreads();
    const float4 bc = *reinterpret_cast<const float4*>(bcast);
    const float m_u = bc.x, m_l = bc.y, du = bc.z, dl = bc.w;

    // phase 2: scale stashed a's and store (float4, coalesced)
#pragma unroll
    for (int c = 0; c < 2; ++c) {
        const int jb = (tid << 3) + (c << 2);
        float4 ocu, ocl;
        float* up = reinterpret_cast<float*>(&ocu);
        float* lp = reinterpret_cast<float*>(&ocl);
#pragma unroll
        for (int k = 0; k < 4; ++k) {
            bool d = (jb + k == i);
            up[k] = d ? du : m_u * au[(c << 2) + k];
            lp[k] = d ? dl : m_l * al[(c << 2) + k];
        }
        const size_t base = (size_t)row * C_ + jb;
        *reinterpret_cast<float4*>(out + OFF_LC + base) = ocl;
        *reinterpret_cast<float4*>(out + OFF_UC + base) = ocu;
    }
}

extern "C" void kernel_launch(void* const* d_in, const int* in_sizes, int n_in,
                              void* d_out, int out_size) {
    const float* lower = (const float*)d_in[0];
    const float* upper = (const float*)d_in[1];
    float* out = (float*)d_out;
    pre_kernel<<<(BC_ + 255) / 256, 256>>>(lower, upper);
    bs_kernel<<<BC_, 128>>>(lower, upper, out);
}

// round 3
// speedup vs baseline: 1.3059x; 1.0894x over previous
#include <cuda_runtime.h>
#include <math.h>

#define B_   16
#define C_   1024
#define BC_  (B_ * C_)
#define EPSf  1e-12f
#define TINYf 1e-9f

#define BCC_    ((size_t)BC_ * (size_t)C_)
#define OFF_SL  ((size_t)0)
#define OFF_SU  ((size_t)BC_)
#define OFF_LC  ((size_t)(2 * BC_))
#define OFF_UC  ((size_t)(2 * BC_) + BCC_)
#define OFF_LB  ((size_t)(2 * BC_) + 2 * BCC_)
#define OFF_UB  ((size_t)(2 * BC_) + 2 * BCC_ + BC_)

// Precomputed per-element exponentials (scratch in __device__ globals)
__device__ float g_El [BC_];   // exp(l)
__device__ float g_Eu [BC_];   // exp(u)
__device__ float g_ElN[BC_];   // exp(-l)
__device__ float g_EuN[BC_];   // exp(-u)

__global__ void pre_kernel(const float* __restrict__ lower,
                           const float* __restrict__ upper) {
    int idx = blockIdx.x * blockDim.x + threadIdx.x;
    if (idx < BC_) {
        float l = lower[idx];
        float u = upper[idx];
        g_El [idx] = expf(l);
        g_Eu [idx] = expf(u);
        g_ElN[idx] = expf(-l);
        g_EuN[idx] = expf(-u);
    }
}

__device__ __forceinline__ float sqrt_apx(float x) {
    float r;
    asm("sqrt.approx.f32 %0, %1;" : "=f"(r) : "f"(x));
    return r;
}

// One block per ROW PAIR (b, 2r) & (b, 2r+1): 256 threads x 4 j's, both rows
// reuse the same register-resident j-chunk -> per-cell load traffic halves.
__global__ __launch_bounds__(256) void bs_kernel(
    const float* __restrict__ lower,
    const float* __restrict__ upper,
    float* __restrict__ out)
{
    const int row0 = blockIdx.x << 1;        // even row (b*C + i0)
    const int b    = row0 >> 10;
    const int i0   = row0 & (C_ - 1);
    const int tid  = threadIdx.x;
    const int j0   = tid << 2;

    const float* __restrict__ lrow = lower + (size_t)b * C_;
    const float* __restrict__ urow = upper + (size_t)b * C_;
    const float* __restrict__ Elb  = g_El  + (size_t)b * C_;
    const float* __restrict__ Eub  = g_Eu  + (size_t)b * C_;

    // per-row scalars for the two rows
    float l_i[2], u_i[2], ElN[2], EuN[2];
#pragma unroll
    for (int r = 0; r < 2; ++r) {
        l_i[r] = __ldg(lrow + i0 + r);
        u_i[r] = __ldg(urow + i0 + r);
        ElN[r] = g_ElN[row0 + r];
        EuN[r] = g_EuN[row0 + r];
    }

    // j-chunk loads: ONCE, reused by both rows
    float4 lj  = *reinterpret_cast<const float4*>(lrow + j0);
    float4 uj  = *reinterpret_cast<const float4*>(urow + j0);
    float4 Elj = *reinterpret_cast<const float4*>(Elb  + j0);
    float4 Euj = *reinterpret_cast<const float4*>(Eub  + j0);
    const float* ljp = reinterpret_cast<const float*>(&lj);
    const float* ujp = reinterpret_cast<const float*>(&uj);
    const float* elp = reinterpret_cast<const float*>(&Elj);
    const float* eup = reinterpret_cast<const float*>(&Euj);

    float au[2][4], al[2][4];
    float sSl[2] = {0.f, 0.f}, sSu[2] = {0.f, 0.f};
    float sAu[2] = {0.f, 0.f}, sAl[2] = {0.f, 0.f};
    float sBu[2] = {0.f, 0.f}, sBl[2] = {0.f, 0.f};

#pragma unroll
    for (int r = 0; r < 2; ++r) {
#pragma unroll
        for (int k = 0; k < 4; ++k) {
            float ld  = ljp[k] - u_i[r];
            float ud  = ujp[k] - l_i[r];
            float el  = elp[k] * EuN[r];       // exp(l_d)
            float eu  = eup[k] * ElN[r];       // exp(u_d)
            float dn  = ud - ld;               // >= 0
            float a_u = __fdividef(eu - el, dn + EPSf);
            if (dn < TINYf) a_u = eu;
            float b_u = el - a_u * ld;
            float a_l = sqrt_apx(el * eu);     // exp((ld+ud)/2)
            float b_l = a_l * fmaf(-0.5f, ld + ud, 1.0f);
            sSl[r] += el;  sSu[r] += eu;
            sAu[r] += a_u; sAl[r] += a_l;
            sBu[r] += b_u; sBl[r] += b_l;
            au[r][k] = a_u;
            al[r][k] = a_l;
        }
    }

    // diagonal correction: owner thread of j==i_r subtracts its contribution
#pragma unroll
    for (int r = 0; r < 2; ++r) {
        const int ir = i0 + r;
        if (tid == (ir >> 2)) {
            float ld  = l_i[r] - u_i[r];
            float ud  = u_i[r] - l_i[r];
            float el  = g_El[row0 + r] * EuN[r];
            float eu  = g_Eu[row0 + r] * ElN[r];
            float dn  = ud - ld;
            float a_u = __fdividef(eu - el, dn + EPSf);
            if (dn < TINYf) a_u = eu;
            float b_u = el - a_u * ld;
            float a_l = sqrt_apx(el * eu);
            float b_l = a_l * fmaf(-0.5f, ld + ud, 1.0f);
            sSl[r] -= el;  sSu[r] -= eu;
            sAu[r] -= a_u; sAl[r] -= a_l;
            sBu[r] -= b_u; sBl[r] -= b_l;
        }
    }

    // butterfly reduce 12 values within each warp
#pragma unroll
    for (int m = 16; m > 0; m >>= 1) {
#pragma unroll
        for (int r = 0; r < 2; ++r) {
            sSl[r] += __shfl_xor_sync(0xffffffffu, sSl[r], m);
            sSu[r] += __shfl_xor_sync(0xffffffffu, sSu[r], m);
            sAu[r] += __shfl_xor_sync(0xffffffffu, sAu[r], m);
            sAl[r] += __shfl_xor_sync(0xffffffffu, sAl[r], m);
            sBu[r] += __shfl_xor_sync(0xffffffffu, sBu[r], m);
            sBl[r] += __shfl_xor_sync(0xffffffffu, sBl[r], m);
        }
    }

    // cross-warp: layout sred[row][var][warp] for the 2 finalize threads
    __shared__ float sred[2][6][8];
    __shared__ float bcast[2][4];
    const int warp = tid >> 5;
    if ((tid & 31) == 0) {
#pragma unroll
        for (int r = 0; r < 2; ++r) {
            sred[r][0][warp] = sSl[r]; sred[r][1][warp] = sSu[r];
            sred[r][2][warp] = sAu[r]; sred[r][3][warp] = sAl[r];
            sred[r][4][warp] = sBu[r]; sred[r][5][warp] = sBl[r];
        }
    }
    __syncthreads();
    if (tid < 2) {
        const int r = tid;
        float acc[6];
#pragma unroll
        for (int v = 0; v < 6; ++v) {
            float s = 0.f;
#pragma unroll
            for (int w = 0; w < 8; ++w) s += sred[r][v][w];
            acc[v] = s;
        }
        const float Sl = acc[0], Su = acc[1], Au = acc[2],
                    Al = acc[3], Bu = acc[4], Bl = acc[5];
        float g_l = __fdividef(1.0f, 1.0f + Sl);
        float g_u = __fdividef(1.0f, 1.0f + Su);
        float dg  = Su - Sl;
        float m_l = -g_u * g_u;
        float m_u = __fdividef(g_u - g_l, dg + EPSf);
        if (fabsf(dg) < TINYf) m_u = m_l;
        float c_u = g_l - m_u * Sl;
        float c_l = g_u - m_l * Su;

        const int row = row0 + r;
        out[OFF_SL + row] = fminf(fmaxf(g_u, 0.0f), 1.0f);
        out[OFF_SU + row] = fminf(fmaxf(g_l, 0.0f), 1.0f);
        out[OFF_LB + row] = m_l * Bl + c_l;
        out[OFF_UB + row] = m_u * Bu + c_u;

        bcast[r][0] = m_u;
        bcast[r][1] = m_l;
        bcast[r][2] = m_u * (-Au);   // diag of upper coef
        bcast[r][3] = m_l * (-Al);   // diag of lower coef
    }
    __syncthreads();

    // store phase: 2 rows x 2 coef arrays, float4 coalesced
#pragma unroll
    for (int r = 0; r < 2; ++r) {
        const float4 bc = *reinterpret_cast<const float4*>(bcast[r]);
        const float m_u = bc.x, m_l = bc.y, du = bc.z, dl = bc.w;
        const int ir = i0 + r;
        float4 ocu, ocl;
        float* up = reinterpret_cast<float*>(&ocu);
        float* lp = reinterpret_cast<float*>(&ocl);
#pragma unroll
        for (int k = 0; k < 4; ++k) {
            bool d = (j0 + k == ir);
            up[k] = d ? du : m_u * au[r][k];
            lp[k] = d ? dl : m_l * al[r][k];
        }
        const size_t base = (size_t)(row0 + r) * C_ + j0;
        *reinterpret_cast<float4*>(out + OFF_LC + base) = ocl;
        *reinterpret_cast<float4*>(out + OFF_UC + base) = ocu;
    }
}

extern "C" void kernel_launch(void* const* d_in, const int* in_sizes, int n_in,
                              void* d_out, int out_size) {
    const float* lower = (const float*)d_in[0];
    const float* upper = (const float*)d_in[1];
    float* out = (float*)d_out;
    pre_kernel<<<(BC_ + 255) / 256, 256>>>(lower, upper);
    bs_kernel<<<BC_ / 2, 256>>>(lower, upper, out);
}

// round 5
// speedup vs baseline: 1.7692x; 1.3548x over previous
#include <cuda_runtime.h>
#include <math.h>

#define B_   16
#define C_   1024
#define BC_  (B_ * C_)
#define EPSf  1e-12f
#define TINYf 1e-9f

#define BCC_    ((size_t)BC_ * (size_t)C_)
#define OFF_SL  ((size_t)0)
#define OFF_SU  ((size_t)BC_)
#define OFF_LC  ((size_t)(2 * BC_))
#define OFF_UC  ((size_t)(2 * BC_) + BCC_)
#define OFF_LB  ((size_t)(2 * BC_) + 2 * BCC_)
#define OFF_UB  ((size_t)(2 * BC_) + 2 * BCC_ + BC_)

// Precomputed per-element exponentials + per-batch sums (no allocation)
__device__ float  g_El [BC_];   // exp(l)
__device__ float  g_Eu [BC_];   // exp(u)
__device__ float  g_ElN[BC_];   // exp(-l)
__device__ float  g_EuN[BC_];   // exp(-u)
__device__ float4 g_Sum[B_];    // (SumEl, SumEu, SumEm, SumEmM) per batch

// One block per batch: compute element exps AND batch sums in one pass.
__global__ __launch_bounds__(1024) void pre_kernel(
    const float* __restrict__ lower,
    const float* __restrict__ upper)
{
    const int b   = blockIdx.x;
    const int t   = threadIdx.x;
    const int idx = b * C_ + t;

    float l  = lower[idx];
    float u  = upper[idx];
    float el = expf(l);
    float eu = expf(u);
    float m  = 0.5f * (l + u);
    float em = expf(m);
    g_El [idx] = el;
    g_Eu [idx] = eu;
    g_ElN[idx] = expf(-l);
    g_EuN[idx] = expf(-u);

    float v0 = el, v1 = eu, v2 = em, v3 = em * m;
#pragma unroll
    for (int s = 16; s > 0; s >>= 1) {
        v0 += __shfl_xor_sync(0xffffffffu, v0, s);
        v1 += __shfl_xor_sync(0xffffffffu, v1, s);
        v2 += __shfl_xor_sync(0xffffffffu, v2, s);
        v3 += __shfl_xor_sync(0xffffffffu, v3, s);
    }
    __shared__ float4 part[32];
    const int warp = t >> 5;
    if ((t & 31) == 0) part[warp] = make_float4(v0, v1, v2, v3);
    __syncthreads();
    if (t == 0) {
        float4 s = make_float4(0.f, 0.f, 0.f, 0.f);
#pragma unroll
        for (int w = 0; w < 32; ++w) {
            s.x += part[w].x; s.y += part[w].y;
            s.z += part[w].z; s.w += part[w].w;
        }
        g_Sum[b] = s;
    }
}

__device__ __forceinline__ float sqrt_apx(float x) {
    float r;
    asm("sqrt.approx.f32 %0, %1;" : "=f"(r) : "f"(x));
    return r;
}

// One block per ROW PAIR: 256 threads x 4 j's per row, j-chunk reused by both
// rows. Only 2 reductions per row (sum a_u, sum a_u*l_j); all other row sums
// are closed-form from per-batch constants.
__global__ __launch_bounds__(256) void bs_kernel(
    const float* __restrict__ lower,
    const float* __restrict__ upper,
    float* __restrict__ out)
{
    const int row0 = blockIdx.x << 1;        // b*C + i0 (even)
    const int b    = row0 >> 10;
    const int i0   = row0 & (C_ - 1);
    const int tid  = threadIdx.x;
    const int j0   = tid << 2;

    const float* __restrict__ lrow = lower + (size_t)b * C_;
    const float* __restrict__ urow = upper + (size_t)b * C_;
    const float* __restrict__ Elb  = g_El  + (size_t)b * C_;
    const float* __restrict__ Eub  = g_Eu  + (size_t)b * C_;

    // per-row scalars
    float w_i[2], ElN[2], EuN[2];
#pragma unroll
    for (int r = 0; r < 2; ++r) {
        w_i[r] = __ldg(urow + i0 + r) - __ldg(lrow + i0 + r);
        ElN[r] = g_ElN[row0 + r];
        EuN[r] = g_EuN[row0 + r];
    }

    // j-chunk loads (once, reused by both rows)
    float4 lj  = *reinterpret_cast<const float4*>(lrow + j0);
    float4 uj  = *reinterpret_cast<const float4*>(urow + j0);
    float4 Elj = *reinterpret_cast<const float4*>(Elb  + j0);
    float4 Euj = *reinterpret_cast<const float4*>(Eub  + j0);
    const float* ljp = reinterpret_cast<const float*>(&lj);
    const float* ujp = reinterpret_cast<const float*>(&uj);
    const float* elp = reinterpret_cast<const float*>(&Elj);
    const float* eup = reinterpret_cast<const float*>(&Euj);

    float wj[4];
#pragma unroll
    for (int k = 0; k < 4; ++k) wj[k] = ujp[k] - ljp[k];

    float au[2][4], al[2][4];
    float sAu[2]  = {0.f, 0.f};
    float sAuL[2] = {0.f, 0.f};

#pragma unroll
    for (int r = 0; r < 2; ++r) {
#pragma unroll
        for (int k = 0; k < 4; ++k) {
            float el  = elp[k] * EuN[r];          // exp(l_j - u_i)
            float eu  = eup[k] * ElN[r];          // exp(u_j - l_i)
            float dn  = wj[k] + w_i[r];           // u_d - l_d >= 0
            float a_u = __fdividef(eu - el, dn + EPSf);
            if (dn < TINYf) a_u = eu;
            float a_l = sqrt_apx(el * eu);        // exp((l_d+u_d)/2)
            sAu[r]  += a_u;
            sAuL[r]  = fmaf(a_u, ljp[k], sAuL[r]);
            au[r][k] = a_u;
            al[r][k] = a_l;
        }
    }

    // butterfly reduce 4 accumulators
#pragma unroll
    for (int s = 16; s > 0; s >>= 1) {
#pragma unroll
        for (int r = 0; r < 2; ++r) {
            sAu[r]  += __shfl_xor_sync(0xffffffffu, sAu[r],  s);
            sAuL[r] += __shfl_xor_sync(0xffffffffu, sAuL[r], s);
        }
    }

    __shared__ float sred[2][2][8];     // [row][var][warp]
    __shared__ float bcast[2][4];
    const int warp = tid >> 5;
    if ((tid & 31) == 0) {
#pragma unroll
        for (int r = 0; r < 2; ++r) {
            sred[r][0][warp] = sAu[r];
            sred[r][1][warp] = sAuL[r];
        }
    }
    __syncthreads();

    if (tid < 2) {
        const int r   = tid;
        const int row = row0 + r;
        float Au = 0.f, AuL = 0.f;
#pragma unroll
        for (int w = 0; w < 8; ++w) {
            Au  += sred[r][0][w];
            AuL += sred[r][1][w];
        }

        // row scalars
        const float l_i  = lrow[i0 + r];
        const float u_i  = urow[i0 + r];
        const float El_i = g_El [row];
        const float Eu_i = g_Eu [row];
        const float ElNi = ElN[r];
        const float EuNi = EuN[r];
        const float wi   = w_i[r];

        // diagonal a_u correction (same expressions as the main loop at j=i)
        {
            float el_d = El_i * EuNi;             // exp(-w_i)
            float eu_d = Eu_i * ElNi;             // exp(+w_i)
            float dn   = wi + wi;
            float a_ud = __fdividef(eu_d - el_d, dn + EPSf);
            if (dn < TINYf) a_ud = eu_d;
            Au  -= a_ud;
            AuL -= a_ud * l_i;
        }

        // closed-form row sums from per-batch constants
        const float4 S = g_Sum[b];                // SumEl, SumEu, SumEm, SumEmM
        const float S_l = EuNi * (S.x - El_i);
        const float S_u = ElNi * (S.y - Eu_i);
        const float m_i  = 0.5f * (l_i + u_i);
        const float Em_i = sqrt_apx(El_i * Eu_i);       // exp(m_i)
        const float EmNi = sqrt_apx(ElNi * EuNi);       // exp(-m_i)
        const float Al = EmNi * (S.z - Em_i);
        const float Bl = (1.0f + m_i) * Al - EmNi * (S.w - Em_i * m_i);
        const float Bu = S_l - AuL + u_i * Au;

        float g_l = __fdividef(1.0f, 1.0f + S_l);
        float g_u = __fdividef(1.0f, 1.0f + S_u);
        float dg  = S_u - S_l;
        float m_l = -g_u * g_u;
        float m_u = __fdividef(g_u - g_l, dg + EPSf);
        if (fabsf(dg) < TINYf) m_u = m_l;
        float c_u = g_l - m_u * S_l;
        float c_l = g_u - m_l * S_u;

        out[OFF_SL + row] = fminf(fmaxf(g_u, 0.0f), 1.0f);
        out[OFF_SU + row] = fminf(fmaxf(g_l, 0.0f), 1.0f);
        out[OFF_LB + row] = m_l * Bl + c_l;
        out[OFF_UB + row] = m_u * Bu + c_u;

        bcast[r][0] = m_u;
        bcast[r][1] = m_l;
        bcast[r][2] = m_u * (-Au);     // diag of upper coef
        bcast[r][3] = m_l * (-Al);     // diag of lower coef
    }
    __syncthreads();

    // store phase: 2 rows x 2 coef arrays, float4 coalesced
#pragma unroll
    for (int r = 0; r < 2; ++r) {
        const float4 bc = *reinterpret_cast<const float4*>(bcast[r]);
        const float m_u = bc.x, m_l = bc.y, du = bc.z, dl = bc.w;
        const int ir = i0 + r;
        float4 ocu, ocl;
        float* up = reinterpret_cast<float*>(&ocu);
        float* lp = reinterpret_cast<float*>(&ocl);
#pragma unroll
        for (int k = 0; k < 4; ++k) {
            bool d = (j0 + k == ir);
            up[k] = d ? du : m_u * au[r][k];
            lp[k] = d ? dl : m_l * al[r][k];
        }
        const size_t base = (size_t)(row0 + r) * C_ + j0;
        *reinterpret_cast<float4*>(out + OFF_LC + base) = ocl;
        *reinterpret_cast<float4*>(out + OFF_UC + base) = ocu;
    }
}

extern "C" void kernel_launch(void* const* d_in, const int* in_sizes, int n_in,
                              void* d_out, int out_size) {
    const float* lower = (const float*)d_in[0];
    const float* upper = (const float*)d_in[1];
    float* out = (float*)d_out;
    pre_kernel<<<B_, 1024>>>(lower, upper);
    bs_kernel<<<BC_ / 2, 256>>>(lower, upper, out);
}